// round 9
// baseline (speedup 1.0000x reference)
#include <cuda_runtime.h>
#include <math.h>

// ---------------------------------------------------------------------------
// Problem constants (fixed by setup_inputs)
// ---------------------------------------------------------------------------
#define NB   2      // batch
#define CMS  8      // band_ms
#define CHS  128    // band_hs
#define HH   512    // hrms/msi spatial
#define HS   128    // hsi spatial
#define QS   32     // q/k spatial (stride-16 / stride-4 outputs)

// ---------------------------------------------------------------------------
// Scratch (static __device__ — no allocation allowed)
// ---------------------------------------------------------------------------
__device__ float g_v[NB*CMS*HH*HH];          // 16 MB: v = lrelu(conv_v(hrms))
__device__ float g_q[NB*CMS*QS*QS];
__device__ float g_k[NB*CHS*QS*QS];
__device__ float g_k0max[NB];
__device__ float g_att[NB*CMS*CHS];
__device__ float g_weff[NB*CMS*9*CHS];       // [n][i][tap][co]

__device__ __forceinline__ float lrelu(float x) { return x >= 0.f ? x : 0.01f * x; }

// packed f32x2 helpers (Blackwell 2x-rate fp32)
#define FMA_F32X2(d, a, b, c) \
    asm("fma.rn.f32x2 %0, %1, %2, %3;" : "=l"(d) : "l"(a), "l"(b), "l"(c))
#define PACK2(out, lo, hi) \
    asm("mov.b64 %0, {%1, %2};" : "=l"(out) : "r"(lo), "r"(hi))
#define UNPACK2(lo, hi, in) \
    asm("mov.b64 {%0, %1}, %2;" : "=r"(lo), "=r"(hi) : "l"(in))

// ---------------------------------------------------------------------------
// K1: conv_v  (8 -> 8, 3x3, stride 1, pad 1) + lrelu      -> g_v
// tile 32x32, 256 threads, thread = (col, 4 vertical pixels) x all 8 couts
// ---------------------------------------------------------------------------
__global__ void __launch_bounds__(256) conv_v_kernel(const float* __restrict__ x,
                                                     const float* __restrict__ Wv,
                                                     const float* __restrict__ bv) {
    __shared__ float s_in[8*34*36];
    __shared__ float s_w[8*9*8];          // [cin][tap][co]
    int n  = blockIdx.z;
    int by = blockIdx.y * 32, bx = blockIdx.x * 32;
    int tid = threadIdx.x;

    for (int e = tid; e < 8*8*9; e += 256) {
        int co = e / 72, rem = e % 72;    // rem = cin*9 + tap
        s_w[rem*8 + co] = Wv[e];
    }
    for (int e = tid; e < 8*34*34; e += 256) {
        int cin = e / 1156, rem = e % 1156, r = rem / 34, c = rem % 34;
        int gh = by - 1 + r, gw = bx - 1 + c;
        float v = 0.f;
        if ((unsigned)gh < (unsigned)HH && (unsigned)gw < (unsigned)HH)
            v = x[((n*CMS + cin)*HH + gh)*HH + gw];
        s_in[(cin*34 + r)*36 + c] = v;
    }
    __syncthreads();

    int lx = tid & 31, ly0 = (tid >> 5) * 4;
    float acc[8][4];
    #pragma unroll
    for (int co = 0; co < 8; co++) {
        float b = bv[co];
        #pragma unroll
        for (int p = 0; p < 4; p++) acc[co][p] = b;
    }
    #pragma unroll
    for (int cin = 0; cin < 8; cin++) {
        float vr[6][3];
        #pragma unroll
        for (int rr = 0; rr < 6; rr++)
            #pragma unroll
            for (int dx = 0; dx < 3; dx++)
                vr[rr][dx] = s_in[(cin*34 + ly0 + rr)*36 + lx + dx];
        #pragma unroll
        for (int tap = 0; tap < 9; tap++) {
            int dy = tap / 3, dx = tap % 3;
            const float* wp = &s_w[(cin*9 + tap)*8];
            #pragma unroll
            for (int co = 0; co < 8; co++) {
                float w = wp[co];
                #pragma unroll
                for (int p = 0; p < 4; p++)
                    acc[co][p] = fmaf(w, vr[p + dy][dx], acc[co][p]);
            }
        }
    }
    #pragma unroll
    for (int co = 0; co < 8; co++)
        #pragma unroll
        for (int p = 0; p < 4; p++)
            g_v[((n*CMS + co)*HH + by + ly0 + p)*HH + bx + lx] = lrelu(acc[co][p]);
}

// ---------------------------------------------------------------------------
// K2: conv_q  (8 -> 8, 3x3, stride 16, pad 1) + lrelu     -> g_q  (tiny)
// ---------------------------------------------------------------------------
__global__ void __launch_bounds__(256) conv_q_kernel(const float* __restrict__ msi,
                                                     const float* __restrict__ Wq,
                                                     const float* __restrict__ bq) {
    int idx = blockIdx.x * 256 + threadIdx.x;
    if (idx >= NB*CMS*QS*QS) return;
    int ox = idx & 31, oy = (idx >> 5) & 31, i = (idx >> 10) & 7, n = idx >> 13;
    float acc = bq[i];
    #pragma unroll
    for (int ci = 0; ci < 8; ci++)
        #pragma unroll
        for (int dy = 0; dy < 3; dy++) {
            int row = oy*16 + dy - 1;
            if ((unsigned)row >= (unsigned)HH) continue;
            #pragma unroll
            for (int dx = 0; dx < 3; dx++) {
                int col = ox*16 + dx - 1;
                if ((unsigned)col >= (unsigned)HH) continue;
                acc = fmaf(Wq[(i*8 + ci)*9 + dy*3 + dx],
                           msi[((n*CMS + ci)*HH + row)*HH + col], acc);
            }
        }
    g_q[idx] = lrelu(acc);
}

// ---------------------------------------------------------------------------
// K3: k0_max[n] = max_i ||q[n,i]||_2
// ---------------------------------------------------------------------------
__global__ void qnorm_kernel() {
    int n = blockIdx.x;
    int warp = threadIdx.x >> 5, lane = threadIdx.x & 31;
    const float* qp = g_q + (n*CMS + warp)*QS*QS;
    float s = 0.f;
    for (int j = lane; j < QS*QS; j += 32) { float v = qp[j]; s += v*v; }
    #pragma unroll
    for (int o = 16; o; o >>= 1) s += __shfl_xor_sync(0xffffffffu, s, o);
    __shared__ float sn[8];
    if (lane == 0) sn[warp] = sqrtf(s);
    __syncthreads();
    if (threadIdx.x == 0) {
        float m = sn[0];
        #pragma unroll
        for (int i = 1; i < 8; i++) m = fmaxf(m, sn[i]);
        g_k0max[n] = m;
    }
}

// ---------------------------------------------------------------------------
// K4: conv_k  (128 -> 128, 3x3, stride 4, pad 1) + lrelu  -> g_k
// block = (coutgrp of 32, out-row-pair, n); 256 threads
// smem input is pre-gathered to only the 3-of-4 columns a stride-4 conv reads
// ---------------------------------------------------------------------------
__global__ void __launch_bounds__(256) conv_k_kernel(const float* __restrict__ hsi,
                                                     const float* __restrict__ Wk,
                                                     const float* __restrict__ bk) {
    __shared__ float s_in[8*6*3*32];     // [ci][irow(=r*3+dy)][dx][x]
    __shared__ float s_w[8*9*33];        // [ci][tap][co32] (pad 33: conflict-free STS)
    int cg = blockIdx.x, rp = blockIdx.y, n = blockIdx.z;
    int tid = threadIdx.x;
    int pos = tid & 63, r = pos >> 5, x = pos & 31;
    int cgsub = tid >> 6;
    int co0 = cg*32 + cgsub*8;

    float acc[8];
    #pragma unroll
    for (int c = 0; c < 8; c++) acc[c] = bk[co0 + c];

    for (int chunk = 0; chunk < 16; chunk++) {
        int cib = chunk * 8;
        // gather input: needed cols are 4x+dx-1, disjoint ranges -> direct map
        for (int e = tid; e < 8*6*128; e += 256) {
            int ci = e / 768, rem = e % 768, irow = rem / 128, t1 = rem % 128;
            int dx = t1 & 3, xx = t1 >> 2;
            if (dx < 3 && xx < 32) {
                int rr = irow / 3, dy = irow % 3;
                int grow = 8*rp + 4*rr + dy - 1;
                int g = t1 - 1;
                float v = 0.f;
                if (g >= 0 && (unsigned)grow < (unsigned)HS)
                    v = hsi[((n*CHS + cib + ci)*HS + grow)*HS + g];
                s_in[((ci*6 + irow)*3 + dx)*32 + xx] = v;
            }
        }
        // weights: coalesced global reads (72-float contiguous runs per cout)
        for (int e = tid; e < 8*9*32; e += 256) {
            int co = e / 72, rem = e % 72, ci = rem / 9, tap = rem % 9;
            s_w[(ci*9 + tap)*33 + co] = Wk[((cg*32 + co)*CHS + cib + ci)*9 + tap];
        }
        __syncthreads();
        #pragma unroll
        for (int ci = 0; ci < 8; ci++) {
            float inr[9];
            #pragma unroll
            for (int dy = 0; dy < 3; dy++)
                #pragma unroll
                for (int dx = 0; dx < 3; dx++)
                    inr[dy*3 + dx] = s_in[((ci*6 + r*3 + dy)*3 + dx)*32 + x];
            #pragma unroll
            for (int tap = 0; tap < 9; tap++) {
                const float* wp = &s_w[(ci*9 + tap)*33 + cgsub*8];
                #pragma unroll
                for (int c = 0; c < 8; c++)
                    acc[c] = fmaf(wp[c], inr[tap], acc[c]);
            }
        }
        __syncthreads();
    }
    int orow = 2*rp + r;
    #pragma unroll
    for (int c = 0; c < 8; c++)
        g_k[((n*CHS + co0 + c)*QS + orow)*QS + x] = lrelu(acc[c]);
}

// ---------------------------------------------------------------------------
// K5: att[n,i,c] = softmax_c( 10/k0max[n] * <q[n,i], k[n,c]> )
// block = (n,i), 128 threads (c)
// ---------------------------------------------------------------------------
__global__ void __launch_bounds__(128) att_kernel() {
    int b = blockIdx.x, n = b >> 3;
    int c = threadIdx.x;
    __shared__ float s_q[QS*QS];
    __shared__ float red[128];
    for (int j = c; j < QS*QS; j += 128) s_q[j] = g_q[b*QS*QS + j];
    __syncthreads();

    const float4* kp = (const float4*)(g_k + (n*CHS + c)*QS*QS);
    const float4* qp = (const float4*)s_q;
    float acc = 0.f;
    #pragma unroll 4
    for (int j = 0; j < QS*QS/4; j++) {
        float4 kv = kp[j], qv = qp[j];
        acc += kv.x*qv.x + kv.y*qv.y + kv.z*qv.z + kv.w*qv.w;
    }
    float s = acc * (10.0f / g_k0max[n]);

    red[c] = s; __syncthreads();
    for (int off = 64; off; off >>= 1) {
        if (c < off) red[c] = fmaxf(red[c], red[c + off]);
        __syncthreads();
    }
    float mx = red[0]; __syncthreads();
    float e = expf(s - mx);
    red[c] = e; __syncthreads();
    for (int off = 64; off; off >>= 1) {
        if (c < off) red[c] += red[c + off];
        __syncthreads();
    }
    g_att[b*CHS + c] = e / red[0];
}

// ---------------------------------------------------------------------------
// K6: Weff[n][i][tap][co] = (1/6) * sum_c Wr[co,c,tap] * att[n,i,c]
// block = (n,i), 128 threads (co); each thread streams its contiguous Wr row
// ---------------------------------------------------------------------------
__global__ void __launch_bounds__(128) weff_kernel(const float* __restrict__ Wr) {
    int b = blockIdx.x;
    int co = threadIdx.x;
    __shared__ float s_att[128];
    s_att[co] = g_att[b*CHS + co];
    __syncthreads();
    float acc[9] = {0,0,0,0,0,0,0,0,0};
    const float* wp = Wr + co*CHS*9;
    for (int c = 0; c < 128; c++) {
        float a = s_att[c];
        #pragma unroll
        for (int tap = 0; tap < 9; tap++) acc[tap] = fmaf(wp[c*9 + tap], a, acc[tap]);
    }
    #pragma unroll
    for (int tap = 0; tap < 9; tap++)
        g_weff[(b*9 + tap)*CHS + co] = acc[tap] * (1.0f/6.0f);
}

// ---------------------------------------------------------------------------
// K7: fused (einsum + conv_r): final = lrelu( conv3x3(v, Weff_n) + br )
// 8 in-ch -> 128 out-ch. tile 32x32, 256 threads, thread = (col, 4 rows).
// cout-PAIRS packed into f32x2: weights pre-packed via ld.shared.v2.u64,
// v replicated once per cin. 2x fp32 FMA rate.
// ---------------------------------------------------------------------------
__global__ void __launch_bounds__(256, 2) final_conv_kernel(const float* __restrict__ br,
                                                            float* __restrict__ out) {
    extern __shared__ float sm[];
    float* s_v = sm;                          // 8*34*36 = 9792 floats
    float* s_w = sm + 8*34*36;                // 8*9*128 = 9216 floats
    int n  = blockIdx.z;
    int by = blockIdx.y * 32, bx = blockIdx.x * 32;
    int tid = threadIdx.x;

    const float* wsrc = g_weff + n*CMS*9*CHS;
    for (int e = tid; e < CMS*9*CHS; e += 256) s_w[e] = wsrc[e];
    for (int e = tid; e < 8*34*34; e += 256) {
        int cin = e / 1156, rem = e % 1156, r = rem / 34, c = rem % 34;
        int gh = by - 1 + r, gw = bx - 1 + c;
        float v = 0.f;
        if ((unsigned)gh < (unsigned)HH && (unsigned)gw < (unsigned)HH)
            v = g_v[((n*CMS + cin)*HH + gh)*HH + gw];
        s_v[(cin*34 + r)*36 + c] = v;
    }
    __syncthreads();

    int lx = tid & 31, ly0 = (tid >> 5) * 4;

    for (int cg = 0; cg < 16; cg++) {
        int co0 = cg * 8;
        unsigned long long acc[4][4];
        #pragma unroll
        for (int j = 0; j < 4; j++) {
            unsigned long long bj;
            PACK2(bj, __float_as_uint(br[co0 + 2*j]), __float_as_uint(br[co0 + 2*j + 1]));
            #pragma unroll
            for (int p = 0; p < 4; p++) acc[j][p] = bj;
        }
        #pragma unroll
        for (int cin = 0; cin < 8; cin++) {
            unsigned long long vrp[6][3];
            #pragma unroll
            for (int rr = 0; rr < 6; rr++)
                #pragma unroll
                for (int dx = 0; dx < 3; dx++) {
                    unsigned vi = __float_as_uint(s_v[(cin*34 + ly0 + rr)*36 + lx + dx]);
                    PACK2(vrp[rr][dx], vi, vi);
                }
            #pragma unroll
            for (int tap = 0; tap < 9; tap++) {
                int dy = tap / 3, dx = tap - dy*3;
                const ulonglong2* wp = (const ulonglong2*)&s_w[(cin*9 + tap)*CHS + co0];
                ulonglong2 wa = wp[0], wb = wp[1];
                unsigned long long wj[4] = {wa.x, wa.y, wb.x, wb.y};
                #pragma unroll
                for (int j = 0; j < 4; j++)
                    #pragma unroll
                    for (int p = 0; p < 4; p++)
                        FMA_F32X2(acc[j][p], wj[j], vrp[p + dy][dx], acc[j][p]);
            }
        }
        #pragma unroll
        for (int j = 0; j < 4; j++)
            #pragma unroll
            for (int p = 0; p < 4; p++) {
                unsigned lo, hi;
                UNPACK2(lo, hi, acc[j][p]);
                float f0 = lrelu(__uint_as_float(lo));
                float f1 = lrelu(__uint_as_float(hi));
                int base = ((n*CHS + co0 + 2*j)*HH + by + ly0 + p)*HH + bx + lx;
                out[base] = f0;
                out[base + HH*HH] = f1;
            }
    }
}

// ---------------------------------------------------------------------------
// Launch
// ---------------------------------------------------------------------------
extern "C" void kernel_launch(void* const* d_in, const int* in_sizes, int n_in,
                              void* d_out, int out_size) {
    (void)in_sizes; (void)n_in; (void)out_size;
    const float* hrms = (const float*)d_in[0];
    const float* msi  = (const float*)d_in[1];
    const float* hsi  = (const float*)d_in[2];
    const float* Wv   = (const float*)d_in[3];
    const float* bv   = (const float*)d_in[4];
    const float* Wq   = (const float*)d_in[5];
    const float* bq   = (const float*)d_in[6];
    const float* Wk   = (const float*)d_in[7];
    const float* bk   = (const float*)d_in[8];
    const float* Wr   = (const float*)d_in[9];
    const float* br   = (const float*)d_in[10];
    float* out = (float*)d_out;

    const int final_smem = (8*34*36 + 8*9*128) * (int)sizeof(float);  // 76032 B
    cudaFuncSetAttribute(final_conv_kernel,
                         cudaFuncAttributeMaxDynamicSharedMemorySize, final_smem);

    conv_v_kernel<<<dim3(16, 16, NB), 256>>>(hrms, Wv, bv);
    conv_q_kernel<<<(NB*CMS*QS*QS + 255)/256, 256>>>(msi, Wq, bq);
    qnorm_kernel<<<NB, 256>>>();
    conv_k_kernel<<<dim3(4, 16, NB), 256>>>(hsi, Wk, bk);
    att_kernel<<<NB*CMS, 128>>>();
    weff_kernel<<<NB*CMS, 128>>>(Wr);
    final_conv_kernel<<<dim3(16, 16, NB), 256, final_smem>>>(br, out);
}

// round 10
// speedup vs baseline: 1.4218x; 1.4218x over previous
#include <cuda_runtime.h>
#include <math.h>

// ---------------------------------------------------------------------------
// Problem constants (fixed by setup_inputs)
// ---------------------------------------------------------------------------
#define NB   2      // batch
#define CMS  8      // band_ms
#define CHS  128    // band_hs
#define HH   512    // hrms/msi spatial
#define HS   128    // hsi spatial
#define QS   32     // q/k spatial
#define KK9  (CHS*9)        // 1152 : im2col K dim
#define NPX  (QS*QS)        // 1024 : pixels per batch
#define SPL  8              // split-K factor
#define KSP  (KK9/SPL)      // 144 per split

typedef unsigned long long ull;

// ---------------------------------------------------------------------------
// Scratch (static __device__ — no allocation allowed)
// ---------------------------------------------------------------------------
__device__ float g_v[NB*CMS*HH*HH];            // 16 MB
__device__ float g_q[NB*CMS*NPX];
__device__ float g_k[NB*CHS*NPX];
__device__ float g_k0max[NB];
__device__ float g_att[NB*CMS*CHS];
__device__ float g_weff[NB*CMS*9*CHS];
__device__ float g_kim[NB*KK9*NPX];            // 9.4 MB im2col
__device__ float g_kpart[SPL*NB*CHS*NPX];      // 8.4 MB split-K partials

__device__ __forceinline__ float lrelu(float x) { return x >= 0.f ? x : 0.01f * x; }

#define FMA_F32X2(d, a, b, c) \
    asm("fma.rn.f32x2 %0, %1, %2, %3;" : "=l"(d) : "l"(a), "l"(b), "l"(c))
#define PACK2(out, lo, hi) \
    asm("mov.b64 %0, {%1, %2};" : "=l"(out) : "r"(lo), "r"(hi))
#define UNPACK2(lo, hi, in) \
    asm("mov.b64 {%0, %1}, %2;" : "=r"(lo), "=r"(hi) : "l"(in))

// ---------------------------------------------------------------------------
// K1: conv_v  (8 -> 8, 3x3, stride 1, pad 1) + lrelu      -> g_v
// ---------------------------------------------------------------------------
__global__ void __launch_bounds__(256) conv_v_kernel(const float* __restrict__ x,
                                                     const float* __restrict__ Wv,
                                                     const float* __restrict__ bv) {
    __shared__ float s_in[8*34*36];
    __shared__ float s_w[8*9*8];
    int n  = blockIdx.z;
    int by = blockIdx.y * 32, bx = blockIdx.x * 32;
    int tid = threadIdx.x;

    for (int e = tid; e < 8*8*9; e += 256) {
        int co = e / 72, rem = e % 72;
        s_w[rem*8 + co] = Wv[e];
    }
    for (int e = tid; e < 8*34*34; e += 256) {
        int cin = e / 1156, rem = e % 1156, r = rem / 34, c = rem % 34;
        int gh = by - 1 + r, gw = bx - 1 + c;
        float v = 0.f;
        if ((unsigned)gh < (unsigned)HH && (unsigned)gw < (unsigned)HH)
            v = x[((n*CMS + cin)*HH + gh)*HH + gw];
        s_in[(cin*34 + r)*36 + c] = v;
    }
    __syncthreads();

    int lx = tid & 31, ly0 = (tid >> 5) * 4;
    float acc[8][4];
    #pragma unroll
    for (int co = 0; co < 8; co++) {
        float b = bv[co];
        #pragma unroll
        for (int p = 0; p < 4; p++) acc[co][p] = b;
    }
    #pragma unroll
    for (int cin = 0; cin < 8; cin++) {
        float vr[6][3];
        #pragma unroll
        for (int rr = 0; rr < 6; rr++)
            #pragma unroll
            for (int dx = 0; dx < 3; dx++)
                vr[rr][dx] = s_in[(cin*34 + ly0 + rr)*36 + lx + dx];
        #pragma unroll
        for (int tap = 0; tap < 9; tap++) {
            int dy = tap / 3, dx = tap % 3;
            const float* wp = &s_w[(cin*9 + tap)*8];
            #pragma unroll
            for (int co = 0; co < 8; co++) {
                float w = wp[co];
                #pragma unroll
                for (int p = 0; p < 4; p++)
                    acc[co][p] = fmaf(w, vr[p + dy][dx], acc[co][p]);
            }
        }
    }
    #pragma unroll
    for (int co = 0; co < 8; co++)
        #pragma unroll
        for (int p = 0; p < 4; p++)
            g_v[((n*CMS + co)*HH + by + ly0 + p)*HH + bx + lx] = lrelu(acc[co][p]);
}

// ---------------------------------------------------------------------------
// K2: conv_q  (8 -> 8, 3x3, stride 16, pad 1) + lrelu     -> g_q
// 64 blocks; 8 threads cooperate per output (one per ci), shfl reduce.
// ---------------------------------------------------------------------------
__global__ void __launch_bounds__(256) conv_q_kernel(const float* __restrict__ msi,
                                                     const float* __restrict__ Wq,
                                                     const float* __restrict__ bq) {
    int b = blockIdx.x;                 // 64 blocks
    int n = b >> 5, i = (b >> 2) & 7, qy = b & 3;
    int tid = threadIdx.x;
    int ox = tid >> 3, ci = tid & 7;    // ci in low lane bits -> in-warp reduce

    __shared__ float s_wq[72];
    if (tid < 72) s_wq[tid] = Wq[i*72 + tid];
    __syncthreads();

    float bias = bq[i];
    for (int r = 0; r < 8; r++) {
        int oy = qy*8 + r;
        float acc = 0.f;
        #pragma unroll
        for (int dy = 0; dy < 3; dy++) {
            int row = oy*16 + dy - 1;
            if ((unsigned)row >= (unsigned)HH) continue;
            #pragma unroll
            for (int dx = 0; dx < 3; dx++) {
                int col = ox*16 + dx - 1;
                if ((unsigned)col >= (unsigned)HH) continue;
                acc = fmaf(s_wq[ci*9 + dy*3 + dx],
                           msi[((n*CMS + ci)*HH + row)*HH + col], acc);
            }
        }
        acc += __shfl_xor_sync(0xffffffffu, acc, 1);
        acc += __shfl_xor_sync(0xffffffffu, acc, 2);
        acc += __shfl_xor_sync(0xffffffffu, acc, 4);
        if (ci == 0)
            g_q[((n*CMS + i)*QS + oy)*QS + ox] = lrelu(acc + bias);
    }
}

// ---------------------------------------------------------------------------
// K3: k0_max[n] = max_i ||q[n,i]||_2
// ---------------------------------------------------------------------------
__global__ void qnorm_kernel() {
    int n = blockIdx.x;
    int warp = threadIdx.x >> 5, lane = threadIdx.x & 31;
    const float* qp = g_q + (n*CMS + warp)*NPX;
    float s = 0.f;
    for (int j = lane; j < NPX; j += 32) { float v = qp[j]; s += v*v; }
    #pragma unroll
    for (int o = 16; o; o >>= 1) s += __shfl_xor_sync(0xffffffffu, s, o);
    __shared__ float sn[8];
    if (lane == 0) sn[warp] = sqrtf(s);
    __syncthreads();
    if (threadIdx.x == 0) {
        float m = sn[0];
        #pragma unroll
        for (int i = 1; i < 8; i++) m = fmaxf(m, sn[i]);
        g_k0max[n] = m;
    }
}

// ---------------------------------------------------------------------------
// K4a: im2col for conv_k  -> g_kim[n][ci*9+tap][px]
// ---------------------------------------------------------------------------
__global__ void __launch_bounds__(256) im2col_k_kernel(const float* __restrict__ hsi) {
    int k = blockIdx.x;                 // 0..1151
    int n = blockIdx.y;
    int ci = k / 9, tap = k % 9;
    int dy = tap / 3, dx = tap % 3;
    const float* src = hsi + (n*CHS + ci)*HS*HS;
    float* dst = g_kim + (n*KK9 + k)*NPX;
    for (int px = threadIdx.x; px < NPX; px += 256) {
        int oy = px >> 5, ox = px & 31;
        int row = 4*oy + dy - 1, col = 4*ox + dx - 1;
        float v = 0.f;
        if ((unsigned)row < (unsigned)HS && (unsigned)col < (unsigned)HS)
            v = src[row*HS + col];
        dst[px] = v;
    }
}

// ---------------------------------------------------------------------------
// K4b: split-K GEMM: part[s][n][co][px] = sum_{k in split s} Wk[co][k]*kim[n][k][px]
// grid (pxg=8, cog=2, n*SPL=16) = 256 blocks, 256 threads.
// Tile 64co x 128px, K=144 in chunks of 16; cout pairs in f32x2.
// ---------------------------------------------------------------------------
__global__ void __launch_bounds__(256) gemm_k_kernel(const float* __restrict__ Wk) {
    __shared__ __align__(16) float s_w[16*68];    // [kk][co64] stride 68
    __shared__ __align__(16) float s_im[16*128];  // [kk][px128]
    int px0 = blockIdx.x * 128;
    int co0 = blockIdx.y * 64;
    int z = blockIdx.z;
    int n = z >> 3, s = z & 7;
    int k0 = s * KSP;
    int tid = threadIdx.x;
    int c8 = tid >> 5, pxq = tid & 31;   // 8 couts, 4 px per thread

    ull acc[4][4];
    #pragma unroll
    for (int j = 0; j < 4; j++)
        #pragma unroll
        for (int p = 0; p < 4; p++) acc[j][p] = 0ull;

    for (int cc = 0; cc < KSP/16; cc++) {
        int kbase = k0 + cc*16;
        #pragma unroll
        for (int e = tid; e < 1024; e += 256) {
            int co = e >> 4, kk = e & 15;
            s_w[kk*68 + co] = Wk[(co0 + co)*KK9 + kbase + kk];
        }
        #pragma unroll
        for (int e = tid; e < 2048; e += 256) {
            int kk = e >> 7, p = e & 127;
            s_im[kk*128 + p] = g_kim[(n*KK9 + kbase + kk)*NPX + px0 + p];
        }
        __syncthreads();
        #pragma unroll
        for (int kk = 0; kk < 16; kk++) {
            const ulonglong2* wp = (const ulonglong2*)&s_w[kk*68 + c8*8];
            ulonglong2 wa = wp[0], wb = wp[1];
            ull wj[4] = {wa.x, wa.y, wb.x, wb.y};
            float4 im = *(const float4*)&s_im[kk*128 + pxq*4];
            float imv[4] = {im.x, im.y, im.z, im.w};
            #pragma unroll
            for (int p = 0; p < 4; p++) {
                unsigned u = __float_as_uint(imv[p]);
                ull vv; PACK2(vv, u, u);
                #pragma unroll
                for (int j = 0; j < 4; j++)
                    FMA_F32X2(acc[j][p], wj[j], vv, acc[j][p]);
            }
        }
        __syncthreads();
    }

    int pbase = (s*NB + n)*CHS;
    #pragma unroll
    for (int j = 0; j < 4; j++) {
        int co = co0 + c8*8 + 2*j;
        #pragma unroll
        for (int p = 0; p < 4; p++) {
            unsigned lo, hi;
            UNPACK2(lo, hi, acc[j][p]);
            int px = px0 + pxq*4 + p;
            g_kpart[(pbase + co    )*NPX + px] = __uint_as_float(lo);
            g_kpart[(pbase + co + 1)*NPX + px] = __uint_as_float(hi);
        }
    }
}

// ---------------------------------------------------------------------------
// K4c: reduce split-K partials + bias + lrelu -> g_k[n][co][px]
// ---------------------------------------------------------------------------
__global__ void __launch_bounds__(256) reduce_k_kernel(const float* __restrict__ bk) {
    int idx4 = blockIdx.x * 256 + threadIdx.x;    // 65536 float4 groups
    int idx = idx4 * 4;
    int co = (idx >> 10) & 127;
    float4 sum = make_float4(0.f, 0.f, 0.f, 0.f);
    #pragma unroll
    for (int s = 0; s < SPL; s++) {
        float4 v = ((const float4*)g_kpart)[s*65536 + idx4];
        sum.x += v.x; sum.y += v.y; sum.z += v.z; sum.w += v.w;
    }
    float b = bk[co];
    float4 o;
    o.x = lrelu(sum.x + b); o.y = lrelu(sum.y + b);
    o.z = lrelu(sum.z + b); o.w = lrelu(sum.w + b);
    ((float4*)g_k)[idx4] = o;
}

// ---------------------------------------------------------------------------
// K5: att[n,i,c] = softmax_c( 10/k0max[n] * <q[n,i], k[n,c]> )
// ---------------------------------------------------------------------------
__global__ void __launch_bounds__(128) att_kernel() {
    int b = blockIdx.x, n = b >> 3;
    int c = threadIdx.x;
    __shared__ float s_q[NPX];
    __shared__ float red[128];
    for (int j = c; j < NPX; j += 128) s_q[j] = g_q[b*NPX + j];
    __syncthreads();

    const float4* kp = (const float4*)(g_k + (n*CHS + c)*NPX);
    const float4* qp = (const float4*)s_q;
    float acc = 0.f;
    #pragma unroll 4
    for (int j = 0; j < NPX/4; j++) {
        float4 kv = kp[j], qv = qp[j];
        acc += kv.x*qv.x + kv.y*qv.y + kv.z*qv.z + kv.w*qv.w;
    }
    float s = acc * (10.0f / g_k0max[n]);

    red[c] = s; __syncthreads();
    for (int off = 64; off; off >>= 1) {
        if (c < off) red[c] = fmaxf(red[c], red[c + off]);
        __syncthreads();
    }
    float mx = red[0]; __syncthreads();
    float e = expf(s - mx);
    red[c] = e; __syncthreads();
    for (int off = 64; off; off >>= 1) {
        if (c < off) red[c] += red[c + off];
        __syncthreads();
    }
    g_att[b*CHS + c] = e / red[0];
}

// ---------------------------------------------------------------------------
// K6: Weff[n][i][tap][co] = (1/6) * sum_c Wr[co,c,tap] * att[n,i,c]
// ---------------------------------------------------------------------------
__global__ void __launch_bounds__(128) weff_kernel(const float* __restrict__ Wr) {
    int b = blockIdx.x;
    int co = threadIdx.x;
    __shared__ float s_att[128];
    s_att[co] = g_att[b*CHS + co];
    __syncthreads();
    float acc[9] = {0,0,0,0,0,0,0,0,0};
    const float* wp = Wr + co*CHS*9;
    for (int c = 0; c < 128; c++) {
        float a = s_att[c];
        #pragma unroll
        for (int tap = 0; tap < 9; tap++) acc[tap] = fmaf(wp[c*9 + tap], a, acc[tap]);
    }
    #pragma unroll
    for (int tap = 0; tap < 9; tap++)
        g_weff[(b*9 + tap)*CHS + co] = acc[tap] * (1.0f/6.0f);
}

// ---------------------------------------------------------------------------
// K7: fused (einsum + conv_r): final = lrelu( conv3x3(v, Weff_n) + br )
// 8 in -> 128 out. tile 32x32, 256 threads, 4 rows each; f32x2 cout pairs.
// v kept scalar in regs, packed on-the-fly (reg relief -> 3 CTAs/SM).
// ---------------------------------------------------------------------------
__global__ void __launch_bounds__(256, 3) final_conv_kernel(const float* __restrict__ br,
                                                            float* __restrict__ out) {
    extern __shared__ float sm[];
    float* s_v = sm;                          // 8*34*36 = 9792 floats
    float* s_w = sm + 8*34*36;                // 8*9*128 = 9216 floats
    int n  = blockIdx.z;
    int by = blockIdx.y * 32, bx = blockIdx.x * 32;
    int tid = threadIdx.x;

    const float* wsrc = g_weff + n*CMS*9*CHS;
    for (int e = tid; e < CMS*9*CHS; e += 256) s_w[e] = wsrc[e];
    for (int e = tid; e < 8*34*34; e += 256) {
        int cin = e / 1156, rem = e % 1156, r = rem / 34, c = rem % 34;
        int gh = by - 1 + r, gw = bx - 1 + c;
        float v = 0.f;
        if ((unsigned)gh < (unsigned)HH && (unsigned)gw < (unsigned)HH)
            v = g_v[((n*CMS + cin)*HH + gh)*HH + gw];
        s_v[(cin*34 + r)*36 + c] = v;
    }
    __syncthreads();

    int lx = tid & 31, ly0 = (tid >> 5) * 4;

    for (int cg = 0; cg < 16; cg++) {
        int co0 = cg * 8;
        ull acc[4][4];
        #pragma unroll
        for (int j = 0; j < 4; j++) {
            ull bj;
            PACK2(bj, __float_as_uint(br[co0 + 2*j]), __float_as_uint(br[co0 + 2*j + 1]));
            #pragma unroll
            for (int p = 0; p < 4; p++) acc[j][p] = bj;
        }
        #pragma unroll
        for (int cin = 0; cin < 8; cin++) {
            float vr[6][3];
            #pragma unroll
            for (int rr = 0; rr < 6; rr++)
                #pragma unroll
                for (int dx = 0; dx < 3; dx++)
                    vr[rr][dx] = s_v[(cin*34 + ly0 + rr)*36 + lx + dx];
            #pragma unroll
            for (int tap = 0; tap < 9; tap++) {
                int dy = tap / 3, dx = tap - dy*3;
                const ulonglong2* wp = (const ulonglong2*)&s_w[(cin*9 + tap)*CHS + co0];
                ulonglong2 wa = wp[0], wb = wp[1];
                ull wj[4] = {wa.x, wa.y, wb.x, wb.y};
                #pragma unroll
                for (int p = 0; p < 4; p++) {
                    unsigned u = __float_as_uint(vr[p + dy][dx]);
                    ull vv; PACK2(vv, u, u);
                    #pragma unroll
                    for (int j = 0; j < 4; j++)
                        FMA_F32X2(acc[j][p], wj[j], vv, acc[j][p]);
                }
            }
        }
        #pragma unroll
        for (int j = 0; j < 4; j++)
            #pragma unroll
            for (int p = 0; p < 4; p++) {
                unsigned lo, hi;
                UNPACK2(lo, hi, acc[j][p]);
                float f0 = lrelu(__uint_as_float(lo));
                float f1 = lrelu(__uint_as_float(hi));
                int base = ((n*CHS + co0 + 2*j)*HH + by + ly0 + p)*HH + bx + lx;
                out[base] = f0;
                out[base + HH*HH] = f1;
            }
    }
}

// ---------------------------------------------------------------------------
// Launch
// ---------------------------------------------------------------------------
extern "C" void kernel_launch(void* const* d_in, const int* in_sizes, int n_in,
                              void* d_out, int out_size) {
    (void)in_sizes; (void)n_in; (void)out_size;
    const float* hrms = (const float*)d_in[0];
    const float* msi  = (const float*)d_in[1];
    const float* hsi  = (const float*)d_in[2];
    const float* Wv   = (const float*)d_in[3];
    const float* bv   = (const float*)d_in[4];
    const float* Wq   = (const float*)d_in[5];
    const float* bq   = (const float*)d_in[6];
    const float* Wk   = (const float*)d_in[7];
    const float* bk   = (const float*)d_in[8];
    const float* Wr   = (const float*)d_in[9];
    const float* br   = (const float*)d_in[10];
    float* out = (float*)d_out;

    const int final_smem = (8*34*36 + 8*9*128) * (int)sizeof(float);  // 76032 B
    cudaFuncSetAttribute(final_conv_kernel,
                         cudaFuncAttributeMaxDynamicSharedMemorySize, final_smem);

    conv_v_kernel<<<dim3(16, 16, NB), 256>>>(hrms, Wv, bv);
    conv_q_kernel<<<64, 256>>>(msi, Wq, bq);
    qnorm_kernel<<<NB, 256>>>();
    im2col_k_kernel<<<dim3(KK9, NB), 256>>>(hsi);
    gemm_k_kernel<<<dim3(8, 2, NB*SPL), 256>>>(Wk);
    reduce_k_kernel<<<256, 256>>>(bk);
    att_kernel<<<NB*CMS, 128>>>();
    weff_kernel<<<NB*CMS, 128>>>(Wr);
    final_conv_kernel<<<dim3(16, 16, NB), 256, final_smem>>>(br, out);
}

// round 12
// speedup vs baseline: 2.2129x; 1.5563x over previous
#include <cuda_runtime.h>
#include <math.h>
#include <cstdint>

// ---------------------------------------------------------------------------
// Problem constants
// ---------------------------------------------------------------------------
#define NB   2
#define CMS  8
#define CHS  128
#define HH   512
#define HS   128
#define QS   32
#define KK9  (CHS*9)        // 1152 : conv_k im2col K
#define NPX  (QS*QS)        // 1024
#define SPL  8
#define KSP  (KK9/SPL)      // 144

typedef unsigned long long ull;

// ---------------------------------------------------------------------------
// Scratch
// ---------------------------------------------------------------------------
__device__ float g_v[NB*CMS*HH*HH];            // 16 MB
__device__ float g_q[NB*CMS*NPX];
__device__ float g_k[NB*CHS*NPX];
__device__ float g_k0max[NB];
__device__ float g_att[NB*CMS*CHS];
__device__ float g_weff[NB*CMS*9*CHS];         // [n][k=cin*9+tap][co]
__device__ float g_kim[NB*KK9*NPX];
__device__ float g_kpart[SPL*NB*CHS*NPX];

__device__ __forceinline__ float lrelu(float x) { return x >= 0.f ? x : 0.01f * x; }

#define FMA_F32X2(d, a, b, c) \
    asm("fma.rn.f32x2 %0, %1, %2, %3;" : "=l"(d) : "l"(a), "l"(b), "l"(c))
#define PACK2(out, lo, hi) \
    asm("mov.b64 %0, {%1, %2};" : "=l"(out) : "r"(lo), "r"(hi))
#define UNPACK2(lo, hi, in) \
    asm("mov.b64 {%0, %1}, %2;" : "=r"(lo), "=r"(hi) : "l"(in))

#define CVT_TF32(out, in) \
    asm("cvt.rna.tf32.f32 %0, %1;" : "=r"(out) : "f"(in))

// ---------------------------------------------------------------------------
// K1: conv_v  (8 -> 8, 3x3, stride 1, pad 1) + lrelu      -> g_v
// ---------------------------------------------------------------------------
__global__ void __launch_bounds__(256) conv_v_kernel(const float* __restrict__ x,
                                                     const float* __restrict__ Wv,
                                                     const float* __restrict__ bv) {
    __shared__ float s_in[8*34*36];
    __shared__ float s_w[8*9*8];
    int n  = blockIdx.z;
    int by = blockIdx.y * 32, bx = blockIdx.x * 32;
    int tid = threadIdx.x;

    for (int e = tid; e < 8*8*9; e += 256) {
        int co = e / 72, rem = e % 72;
        s_w[rem*8 + co] = Wv[e];
    }
    for (int e = tid; e < 8*34*34; e += 256) {
        int cin = e / 1156, rem = e % 1156, r = rem / 34, c = rem % 34;
        int gh = by - 1 + r, gw = bx - 1 + c;
        float v = 0.f;
        if ((unsigned)gh < (unsigned)HH && (unsigned)gw < (unsigned)HH)
            v = x[((n*CMS + cin)*HH + gh)*HH + gw];
        s_in[(cin*34 + r)*36 + c] = v;
    }
    __syncthreads();

    int lx = tid & 31, ly0 = (tid >> 5) * 4;
    float acc[8][4];
    #pragma unroll
    for (int co = 0; co < 8; co++) {
        float b = bv[co];
        #pragma unroll
        for (int p = 0; p < 4; p++) acc[co][p] = b;
    }
    #pragma unroll
    for (int cin = 0; cin < 8; cin++) {
        float vr[6][3];
        #pragma unroll
        for (int rr = 0; rr < 6; rr++)
            #pragma unroll
            for (int dx = 0; dx < 3; dx++)
                vr[rr][dx] = s_in[(cin*34 + ly0 + rr)*36 + lx + dx];
        #pragma unroll
        for (int tap = 0; tap < 9; tap++) {
            int dy = tap / 3, dx = tap % 3;
            const float* wp = &s_w[(cin*9 + tap)*8];
            #pragma unroll
            for (int co = 0; co < 8; co++) {
                float w = wp[co];
                #pragma unroll
                for (int p = 0; p < 4; p++)
                    acc[co][p] = fmaf(w, vr[p + dy][dx], acc[co][p]);
            }
        }
    }
    #pragma unroll
    for (int co = 0; co < 8; co++)
        #pragma unroll
        for (int p = 0; p < 4; p++)
            g_v[((n*CMS + co)*HH + by + ly0 + p)*HH + bx + lx] = lrelu(acc[co][p]);
}

// ---------------------------------------------------------------------------
// K2: conv_q  (8 -> 8, 3x3, stride 16, pad 1) + lrelu     -> g_q
// ---------------------------------------------------------------------------
__global__ void __launch_bounds__(256) conv_q_kernel(const float* __restrict__ msi,
                                                     const float* __restrict__ Wq,
                                                     const float* __restrict__ bq) {
    int b = blockIdx.x;
    int n = b >> 5, i = (b >> 2) & 7, qy = b & 3;
    int tid = threadIdx.x;
    int ox = tid >> 3, ci = tid & 7;

    __shared__ float s_wq[72];
    if (tid < 72) s_wq[tid] = Wq[i*72 + tid];
    __syncthreads();

    float bias = bq[i];
    for (int r = 0; r < 8; r++) {
        int oy = qy*8 + r;
        float acc = 0.f;
        #pragma unroll
        for (int dy = 0; dy < 3; dy++) {
            int row = oy*16 + dy - 1;
            if ((unsigned)row >= (unsigned)HH) continue;
            #pragma unroll
            for (int dx = 0; dx < 3; dx++) {
                int col = ox*16 + dx - 1;
                if ((unsigned)col >= (unsigned)HH) continue;
                acc = fmaf(s_wq[ci*9 + dy*3 + dx],
                           msi[((n*CMS + ci)*HH + row)*HH + col], acc);
            }
        }
        acc += __shfl_xor_sync(0xffffffffu, acc, 1);
        acc += __shfl_xor_sync(0xffffffffu, acc, 2);
        acc += __shfl_xor_sync(0xffffffffu, acc, 4);
        if (ci == 0)
            g_q[((n*CMS + i)*QS + oy)*QS + ox] = lrelu(acc + bias);
    }
}

// ---------------------------------------------------------------------------
// K3: k0_max
// ---------------------------------------------------------------------------
__global__ void qnorm_kernel() {
    int n = blockIdx.x;
    int warp = threadIdx.x >> 5, lane = threadIdx.x & 31;
    const float* qp = g_q + (n*CMS + warp)*NPX;
    float s = 0.f;
    for (int j = lane; j < NPX; j += 32) { float v = qp[j]; s += v*v; }
    #pragma unroll
    for (int o = 16; o; o >>= 1) s += __shfl_xor_sync(0xffffffffu, s, o);
    __shared__ float sn[8];
    if (lane == 0) sn[warp] = sqrtf(s);
    __syncthreads();
    if (threadIdx.x == 0) {
        float m = sn[0];
        #pragma unroll
        for (int i = 1; i < 8; i++) m = fmaxf(m, sn[i]);
        g_k0max[n] = m;
    }
}

// ---------------------------------------------------------------------------
// K4a: im2col for conv_k
// ---------------------------------------------------------------------------
__global__ void __launch_bounds__(256) im2col_k_kernel(const float* __restrict__ hsi) {
    int k = blockIdx.x;
    int n = blockIdx.y;
    int ci = k / 9, tap = k % 9;
    int dy = tap / 3, dx = tap % 3;
    const float* src = hsi + (n*CHS + ci)*HS*HS;
    float* dst = g_kim + (n*KK9 + k)*NPX;
    for (int px = threadIdx.x; px < NPX; px += 256) {
        int oy = px >> 5, ox = px & 31;
        int row = 4*oy + dy - 1, col = 4*ox + dx - 1;
        float v = 0.f;
        if ((unsigned)row < (unsigned)HS && (unsigned)col < (unsigned)HS)
            v = src[row*HS + col];
        dst[px] = v;
    }
}

// ---------------------------------------------------------------------------
// K4b: split-K GEMM for conv_k (f32x2)
// ---------------------------------------------------------------------------
__global__ void __launch_bounds__(256) gemm_k_kernel(const float* __restrict__ Wk) {
    __shared__ __align__(16) float s_w[16*68];
    __shared__ __align__(16) float s_im[16*128];
    int px0 = blockIdx.x * 128;
    int co0 = blockIdx.y * 64;
    int z = blockIdx.z;
    int n = z >> 3, s = z & 7;
    int k0 = s * KSP;
    int tid = threadIdx.x;
    int c8 = tid >> 5, pxq = tid & 31;

    ull acc[4][4];
    #pragma unroll
    for (int j = 0; j < 4; j++)
        #pragma unroll
        for (int p = 0; p < 4; p++) acc[j][p] = 0ull;

    for (int cc = 0; cc < KSP/16; cc++) {
        int kbase = k0 + cc*16;
        #pragma unroll
        for (int e = tid; e < 1024; e += 256) {
            int co = e >> 4, kk = e & 15;
            s_w[kk*68 + co] = Wk[(co0 + co)*KK9 + kbase + kk];
        }
        #pragma unroll
        for (int e = tid; e < 2048; e += 256) {
            int kk = e >> 7, p = e & 127;
            s_im[kk*128 + p] = g_kim[(n*KK9 + kbase + kk)*NPX + px0 + p];
        }
        __syncthreads();
        #pragma unroll
        for (int kk = 0; kk < 16; kk++) {
            const ulonglong2* wp = (const ulonglong2*)&s_w[kk*68 + c8*8];
            ulonglong2 wa = wp[0], wb = wp[1];
            ull wj[4] = {wa.x, wa.y, wb.x, wb.y};
            float4 im = *(const float4*)&s_im[kk*128 + pxq*4];
            float imv[4] = {im.x, im.y, im.z, im.w};
            #pragma unroll
            for (int p = 0; p < 4; p++) {
                unsigned u = __float_as_uint(imv[p]);
                ull vv; PACK2(vv, u, u);
                #pragma unroll
                for (int j = 0; j < 4; j++)
                    FMA_F32X2(acc[j][p], wj[j], vv, acc[j][p]);
            }
        }
        __syncthreads();
    }

    int pbase = (s*NB + n)*CHS;
    #pragma unroll
    for (int j = 0; j < 4; j++) {
        int co = co0 + c8*8 + 2*j;
        #pragma unroll
        for (int p = 0; p < 4; p++) {
            unsigned lo, hi;
            UNPACK2(lo, hi, acc[j][p]);
            int px = px0 + pxq*4 + p;
            g_kpart[(pbase + co    )*NPX + px] = __uint_as_float(lo);
            g_kpart[(pbase + co + 1)*NPX + px] = __uint_as_float(hi);
        }
    }
}

// ---------------------------------------------------------------------------
// K4c: reduce split-K partials + bias + lrelu -> g_k
// ---------------------------------------------------------------------------
__global__ void __launch_bounds__(256) reduce_k_kernel(const float* __restrict__ bk) {
    int idx4 = blockIdx.x * 256 + threadIdx.x;
    int idx = idx4 * 4;
    int co = (idx >> 10) & 127;
    float4 sum = make_float4(0.f, 0.f, 0.f, 0.f);
    #pragma unroll
    for (int s = 0; s < SPL; s++) {
        float4 v = ((const float4*)g_kpart)[s*65536 + idx4];
        sum.x += v.x; sum.y += v.y; sum.z += v.z; sum.w += v.w;
    }
    float b = bk[co];
    float4 o;
    o.x = lrelu(sum.x + b); o.y = lrelu(sum.y + b);
    o.z = lrelu(sum.z + b); o.w = lrelu(sum.w + b);
    ((float4*)g_k)[idx4] = o;
}

// ---------------------------------------------------------------------------
// K5: attention softmax
// ---------------------------------------------------------------------------
__global__ void __launch_bounds__(128) att_kernel() {
    int b = blockIdx.x, n = b >> 3;
    int c = threadIdx.x;
    __shared__ float s_q[NPX];
    __shared__ float red[128];
    for (int j = c; j < NPX; j += 128) s_q[j] = g_q[b*NPX + j];
    __syncthreads();

    const float4* kp = (const float4*)(g_k + (n*CHS + c)*NPX);
    const float4* qp = (const float4*)s_q;
    float acc = 0.f;
    #pragma unroll 4
    for (int j = 0; j < NPX/4; j++) {
        float4 kv = kp[j], qv = qp[j];
        acc += kv.x*qv.x + kv.y*qv.y + kv.z*qv.z + kv.w*qv.w;
    }
    float s = acc * (10.0f / g_k0max[n]);

    red[c] = s; __syncthreads();
    for (int off = 64; off; off >>= 1) {
        if (c < off) red[c] = fmaxf(red[c], red[c + off]);
        __syncthreads();
    }
    float mx = red[0]; __syncthreads();
    float e = expf(s - mx);
    red[c] = e; __syncthreads();
    for (int off = 64; off; off >>= 1) {
        if (c < off) red[c] += red[c + off];
        __syncthreads();
    }
    g_att[b*CHS + c] = e / red[0];
}

// ---------------------------------------------------------------------------
// K6: Weff[n][k=i*9+tap][co] = (1/6) * sum_c Wr[co,c,tap] * att[n,i,c]
// ---------------------------------------------------------------------------
__global__ void __launch_bounds__(128) weff_kernel(const float* __restrict__ Wr) {
    int b = blockIdx.x;
    int co = threadIdx.x;
    __shared__ float s_att[128];
    s_att[co] = g_att[b*CHS + co];
    __syncthreads();
    float acc[9] = {0,0,0,0,0,0,0,0,0};
    const float* wp = Wr + co*CHS*9;
    for (int c = 0; c < 128; c++) {
        float a = s_att[c];
        #pragma unroll
        for (int tap = 0; tap < 9; tap++) acc[tap] = fmaf(wp[c*9 + tap], a, acc[tap]);
    }
    #pragma unroll
    for (int tap = 0; tap < 9; tap++)
        g_weff[(b*9 + tap)*CHS + co] = acc[tap] * (1.0f/6.0f);
}

// ---------------------------------------------------------------------------
// K7: final conv via mma.sync tf32 (baseline PTX tensor op; no 'a' features).
//   Per batch: D[px, co] = A[px, k=72] * B[k, co=128], fp32 accum.
//   CTA = one image row (512 px). M=512 as 32 m16-tiles; 8 warps x 4 tiles.
//   A fragments gathered from halo smem via per-lane k->offset tables.
//   B (tf32 Weff) in smem [k][co] stride 136 (conflict-free B-frag LDS).
//   D stores: 8 consecutive px per co -> full 32B sectors, no transpose.
// ---------------------------------------------------------------------------
#define HALO_STRIDE 516
#define HALO_FLOATS (8*3*HALO_STRIDE)     // 12384
#define BSTR 136
#define B_FLOATS (72*BSTR)                // 9792
#define FINAL_SMEM ((HALO_FLOATS + B_FLOATS + 128) * 4)   // 89216 B

__global__ void __launch_bounds__(256) final_mma_kernel(const float* __restrict__ br,
                                                        float* __restrict__ out) {
    extern __shared__ float sm[];
    float*    s_halo = sm;                                   // 12384 floats
    uint32_t* s_B    = (uint32_t*)(sm + HALO_FLOATS);        // 9792 (tf32)
    float*    s_br   = sm + HALO_FLOATS + B_FLOATS;          // 128

    int y = blockIdx.x;
    int n = blockIdx.y;
    int tid = threadIdx.x;
    int lane = tid & 31, w = tid >> 5;

    // --- B = Weff (tf32) into smem [k][co], stride 136 ---
    const float* wsrc = g_weff + n*72*128;
    for (int e = tid; e < 72*128; e += 256) {
        int k = e >> 7, co = e & 127;
        uint32_t t; CVT_TF32(t, wsrc[k*128 + co]);
        s_B[k*BSTR + co] = t;
    }
    if (tid < 128) s_br[tid] = br[tid];

    // --- halo: 8 cin x 3 rows x 514 cols (col c <-> gw = c-1) ---
    for (int e = tid; e < 8*3*514; e += 256) {
        int cin = e / 1542, rem = e % 1542, r = rem / 514, c = rem % 514;
        int gh = y - 1 + r, gw = c - 1;
        float v = 0.f;
        if ((unsigned)gh < (unsigned)HH && (unsigned)gw < (unsigned)HH)
            v = g_v[((n*CMS + cin)*HH + gh)*HH + gw];
        s_halo[(cin*3 + r)*HALO_STRIDE + c] = v;
    }
    __syncthreads();

    // --- per-lane k -> halo-offset tables (k = cin*9 + dy*3 + dx) ---
    int off0[9], off1[9];
    #pragma unroll
    for (int kk = 0; kk < 9; kk++) {
        int k = kk*8 + (lane & 3);
        int cin = k / 9, tap = k % 9;
        off0[kk] = (cin*3 + tap/3)*HALO_STRIDE + (tap%3);
        k += 4; cin = k / 9; tap = k % 9;
        off1[kk] = (cin*3 + tap/3)*HALO_STRIDE + (tap%3);
    }

    float* orow = out + (size_t)(n*CHS) * (HH*HH) + (size_t)y * HH;
    const size_t plane = (size_t)HH * HH;

    for (int i = 0; i < 4; i++) {
        int x0 = (w + 8*i) * 16;
        int x  = x0 + (lane >> 2);

        // A fragments for all 9 k-steps (halo col = x_img + dx, baked into off)
        uint32_t a[9][4];
        #pragma unroll
        for (int kk = 0; kk < 9; kk++) {
            float f0 = s_halo[off0[kk] + x];
            float f1 = s_halo[off0[kk] + x + 8];
            float f2 = s_halo[off1[kk] + x];
            float f3 = s_halo[off1[kk] + x + 8];
            CVT_TF32(a[kk][0], f0);
            CVT_TF32(a[kk][1], f1);
            CVT_TF32(a[kk][2], f2);
            CVT_TF32(a[kk][3], f3);
        }

        #pragma unroll 4
        for (int nt = 0; nt < 16; nt++) {
            int n0  = nt * 8;
            int co0 = n0 + 2*(lane & 3);
            float d0 = s_br[co0], d1 = s_br[co0 + 1];
            float d2 = d0,        d3 = d1;
            const uint32_t* bp = &s_B[(lane & 3)*BSTR + n0 + (lane >> 2)];
            #pragma unroll
            for (int kk = 0; kk < 9; kk++) {
                uint32_t b0 = bp[(kk*8    )*BSTR];
                uint32_t b1 = bp[(kk*8 + 4)*BSTR];
                asm("mma.sync.aligned.m16n8k8.row.col.f32.tf32.tf32.f32 "
                    "{%0,%1,%2,%3}, {%4,%5,%6,%7}, {%8,%9}, {%0,%1,%2,%3};"
                    : "+f"(d0), "+f"(d1), "+f"(d2), "+f"(d3)
                    : "r"(a[kk][0]), "r"(a[kk][1]), "r"(a[kk][2]), "r"(a[kk][3]),
                      "r"(b0), "r"(b1));
            }
            orow[(size_t)co0      *plane + x    ] = lrelu(d0);
            orow[(size_t)(co0 + 1)*plane + x    ] = lrelu(d1);
            orow[(size_t)co0      *plane + x + 8] = lrelu(d2);
            orow[(size_t)(co0 + 1)*plane + x + 8] = lrelu(d3);
        }
    }
}

// ---------------------------------------------------------------------------
// Launch
// ---------------------------------------------------------------------------
extern "C" void kernel_launch(void* const* d_in, const int* in_sizes, int n_in,
                              void* d_out, int out_size) {
    (void)in_sizes; (void)n_in; (void)out_size;
    const float* hrms = (const float*)d_in[0];
    const float* msi  = (const float*)d_in[1];
    const float* hsi  = (const float*)d_in[2];
    const float* Wv   = (const float*)d_in[3];
    const float* bv   = (const float*)d_in[4];
    const float* Wq   = (const float*)d_in[5];
    const float* bq   = (const float*)d_in[6];
    const float* Wk   = (const float*)d_in[7];
    const float* bk   = (const float*)d_in[8];
    const float* Wr   = (const float*)d_in[9];
    const float* br   = (const float*)d_in[10];
    float* out = (float*)d_out;

    cudaFuncSetAttribute(final_mma_kernel,
                         cudaFuncAttributeMaxDynamicSharedMemorySize, FINAL_SMEM);

    conv_v_kernel<<<dim3(16, 16, NB), 256>>>(hrms, Wv, bv);
    conv_q_kernel<<<64, 256>>>(msi, Wq, bq);
    qnorm_kernel<<<NB, 256>>>();
    im2col_k_kernel<<<dim3(KK9, NB), 256>>>(hsi);
    gemm_k_kernel<<<dim3(8, 2, NB*SPL), 256>>>(Wk);
    reduce_k_kernel<<<256, 256>>>(bk);
    att_kernel<<<NB*CMS, 128>>>();
    weff_kernel<<<NB*CMS, 128>>>(Wr);
    final_mma_kernel<<<dim3(HH, NB), 256, FINAL_SMEM>>>(br, out);
}